// round 15
// baseline (speedup 1.0000x reference)
#include <cuda_runtime.h>
#include <cuda_bf16.h>
#include <math.h>
#include <stdint.h>

#define B_    8
#define SP    128
#define ST    64
#define SV    64
#define SEQ   256
#define DMODEL 768
#define DLLM  4096
#define NH    32
#define HD    128
#define DFF   11008
#define NTOK  (B_*SEQ)
#define QKVS  (3*DLLM)
#define GUS   (2*DFF)
#define EPS   1e-5f

// ---------------- fp32 scratch ----------------
#define SZ_TOKD ((size_t)NTOK*DLLM)
#define SZ_FF   ((size_t)NTOK*DFF)
#define OFF_H    ((size_t)0)
#define OFF_XN   (SZ_TOKD)
#define OFF_QKV  (2*SZ_TOKD)
#define OFF_GU   (5*SZ_TOKD)
#define OFF_COS  (OFF_GU + 2*SZ_FF)
#define OFF_SIN  (OFF_COS + (size_t)SEQ*64)
#define OFF_POOL (OFF_SIN + (size_t)SEQ*64)
#define OFF_Y1   (OFF_POOL + (size_t)B_*DLLM)
#define SCRATCH_TOTAL (OFF_Y1 + (size_t)B_*768)
__device__ float g_scratch[SCRATCH_TOTAL];

// ---------------- bf16 scratch (activations only now) ----------------
#define SZ_TV  ((size_t)512*DMODEL)
#define BO_XNH  ((size_t)0)
#define BO_XNL  (BO_XNH + SZ_TOKD)
#define BO_ATH  (BO_XNL + SZ_TOKD)
#define BO_ATL  (BO_ATH + SZ_TOKD)
#define BO_GH   (BO_ATL + SZ_TOKD)
#define BO_GL   (BO_GH + SZ_FF)
#define BO_TXH  (BO_GL + SZ_FF)
#define BO_TXL  (BO_TXH + SZ_TV)
#define BO_VXH  (BO_TXL + SZ_TV)
#define BO_VXL  (BO_VXH + SZ_TV)
#define BF_TOTAL (BO_VXL + SZ_TV)
__device__ __align__(256) __nv_bfloat16 g_bf[BF_TOTAL];

// ---------------- helpers ----------------
__device__ __forceinline__ uint32_t smem_u32(const void* p) {
    uint32_t a;
    asm("{ .reg .u64 t; cvta.to.shared.u64 t, %1; cvt.u32.u64 %0, t; }" : "=r"(a) : "l"(p));
    return a;
}
__device__ __forceinline__ void cp16(uint32_t d, const void* s) {
    asm volatile("cp.async.cg.shared.global [%0], [%1], 16;" :: "r"(d), "l"(s));
}
__device__ __forceinline__ void split_bf(float x, __nv_bfloat16& h, __nv_bfloat16& l) {
    h = __float2bfloat16_rn(x);
    l = __float2bfloat16_rn(x - __bfloat162float(h));
}
__device__ __forceinline__ void mma_bf16(float* c,
    uint32_t a0, uint32_t a1, uint32_t a2, uint32_t a3, uint32_t b0, uint32_t b1) {
    asm volatile(
        "mma.sync.aligned.m16n8k16.row.col.f32.bf16.bf16.f32 "
        "{%0,%1,%2,%3}, {%4,%5,%6,%7}, {%8,%9}, {%0,%1,%2,%3};"
        : "+f"(c[0]), "+f"(c[1]), "+f"(c[2]), "+f"(c[3])
        : "r"(a0), "r"(a1), "r"(a2), "r"(a3), "r"(b0), "r"(b1));
}
__device__ __forceinline__ void ldm_x4(uint32_t& r0, uint32_t& r1,
                                       uint32_t& r2, uint32_t& r3, uint32_t a) {
    asm volatile("ldmatrix.sync.aligned.m8n8.x4.shared.b16 {%0,%1,%2,%3}, [%4];"
        : "=r"(r0), "=r"(r1), "=r"(r2), "=r"(r3) : "r"(a));
}
__device__ __forceinline__ void ldm_x4t(uint32_t& r0, uint32_t& r1,
                                        uint32_t& r2, uint32_t& r3, uint32_t a) {
    asm volatile("ldmatrix.sync.aligned.m8n8.x4.trans.shared.b16 {%0,%1,%2,%3}, [%4];"
        : "=r"(r0), "=r"(r1), "=r"(r2), "=r"(r3) : "r"(a));
}

// ---------------------------------------------------------------------------
// bf16-split GEMM: C[M,N] = A[M,K] @ W[K,N]. A = Ah+Al bf16 [M,K].
// B is ORIGINAL fp32 [K,Nsub] (up to 3 sub-matrices fused along N); loader
// threads convert to bf16 hi/lo in-kernel (identical split values/layout as
// the old pre-pass). BM=128, BN=64, BK=32; B fragments via ldmatrix.trans.
// 3 passes AhBh + AhBl + AlBh, fp32 accum, 3-stage A cp.async, 2 CTAs/SM.
// flags: 1 accumulate, 2 bias, 4 row remap.
// ---------------------------------------------------------------------------
#define TPITCH 40
#define BPITCH 72
#define O_AH 0
#define O_AL (128*TPITCH)
#define O_BH (256*TPITCH)
#define O_BL (O_BH + 32*BPITCH)
#define STAGE_E (O_BH + 64*BPITCH)
#define GSMEM_BYTES (3*STAGE_E*2)

__global__ __launch_bounds__(256, 2) void gemm_tc(
    const __nv_bfloat16* __restrict__ Ah, const __nv_bfloat16* __restrict__ Al,
    const float* __restrict__ B0, const float* __restrict__ B1,
    const float* __restrict__ B2, int Nsub,
    float* __restrict__ C, int M, int N, int K,
    int flags, const float* __restrict__ bias, int map_base)
{
    extern __shared__ __nv_bfloat16 sm[];
    const int tid = threadIdx.x;
    const int wid = tid >> 5, lane = tid & 31;
    const int wm = wid & 3, wn = wid >> 2;
    const int m0 = blockIdx.y * 128, n0 = blockIdx.x * 64;
    const int gr = lane >> 2, qc = lane & 3;
    const uint32_t smbase = smem_u32(sm);

    const uint32_t aoff = (uint32_t)(((wm * 32 + (lane & 15)) * TPITCH + ((lane >> 4) << 3)) * 2);
    const int bko = ((lane >> 3) & 1) * 8 + (lane & 7);
    const int bno = wn * 32 + ((lane >> 4) << 3);

    // B sub-matrix selection (n-tile lies entirely within one sub-matrix)
    const int sub = n0 / Nsub;
    const float* Bp = (sub == 0) ? B0 : (sub == 1) ? B1 : B2;
    const int col0 = n0 - sub * Nsub;

    // A loader: 1024 16B chunks / stage via cp.async, 4 per thread
    const __nv_bfloat16* gpA[4];
    uint32_t soffA[4];
#pragma unroll
    for (int i = 0; i < 4; i++) {
        int c = tid + i * 256;
        const __nv_bfloat16* base = (c < 512) ? Ah : Al;
        int local = c & 511;
        int row = local >> 2, subk = local & 3;
        gpA[i] = base + (size_t)(m0 + row) * K + subk * 8;
        soffA[i] = (uint32_t)((((c < 512) ? O_AH : O_AL) + row * TPITCH + subk * 8) * 2);
    }

    // B loader: each thread owns 8 fp32 of one k-row per stage
    const int bkrow = tid >> 3, bsub8 = tid & 7;
    const float4* gB = reinterpret_cast<const float4*>(
        Bp + (size_t)bkrow * Nsub + col0 + bsub8 * 8);
    const size_t badv4 = (size_t)8 * Nsub;        // float4s per 32-row stage
    const uint32_t bsts_h = (uint32_t)((O_BH + bkrow * BPITCH + bsub8 * 8) * 2);
    const uint32_t bsts_l = (uint32_t)((O_BL + bkrow * BPITCH + bsub8 * 8) * 2);

#define LOAD_A(s_) do { \
    uint32_t sb_ = smbase + (uint32_t)(((s_) % 3) * STAGE_E * 2); \
    _Pragma("unroll") \
    for (int i_ = 0; i_ < 4; i_++) \
        cp16(sb_ + soffA[i_], gpA[i_] + (size_t)(s_) * 32); \
    asm volatile("cp.async.commit_group;" ::: "memory"); \
} while (0)

#define LDB(s_, p_) do { \
    size_t o_ = (size_t)(s_) * badv4; \
    breg[p_][0] = gB[o_]; breg[p_][1] = gB[o_ + 1]; \
} while (0)

#define STB(s_, p_) do { \
    __nv_bfloat16* stp_ = sm + ((s_) % 3) * STAGE_E; \
    __align__(16) __nv_bfloat16 hb_[8], lb_[8]; \
    float4 v0_ = breg[p_][0], v1_ = breg[p_][1]; \
    split_bf(v0_.x, hb_[0], lb_[0]); split_bf(v0_.y, hb_[1], lb_[1]); \
    split_bf(v0_.z, hb_[2], lb_[2]); split_bf(v0_.w, hb_[3], lb_[3]); \
    split_bf(v1_.x, hb_[4], lb_[4]); split_bf(v1_.y, hb_[5], lb_[5]); \
    split_bf(v1_.z, hb_[6], lb_[6]); split_bf(v1_.w, hb_[7], lb_[7]); \
    *reinterpret_cast<uint4*>(reinterpret_cast<char*>(stp_) + bsts_h) = \
        *reinterpret_cast<uint4*>(hb_); \
    *reinterpret_cast<uint4*>(reinterpret_cast<char*>(stp_) + bsts_l) = \
        *reinterpret_cast<uint4*>(lb_); \
} while (0)

    const int S = K / 32;
    float4 breg[2][2];
    LOAD_A(0);
    LOAD_A(1);
    LDB(0, 0);
    LDB(1, 1);

    float acc[2][4][4];
#pragma unroll
    for (int t = 0; t < 2; t++)
#pragma unroll
        for (int n = 0; n < 4; n++)
#pragma unroll
            for (int e = 0; e < 4; e++) acc[t][n][e] = 0.f;

    for (int s = 0; s < S; s++) {
        const int p = s & 1;
        asm volatile("cp.async.wait_group 1;" ::: "memory");
        STB(s, p);
        __syncthreads();
        if (s + 2 < S) { LOAD_A(s + 2); LDB(s + 2, p); }
        else { asm volatile("cp.async.commit_group;" ::: "memory"); }

        const uint32_t stg = smbase + (uint32_t)((s % 3) * STAGE_E * 2);

#pragma unroll
        for (int kk = 0; kk < 32; kk += 16) {
            uint32_t ah[2][4], al[2][4], bh[4][2], bl[4][2];
#pragma unroll
            for (int t = 0; t < 2; t++) {
                uint32_t off = aoff + (uint32_t)((t * 16 * TPITCH + kk) * 2);
                ldm_x4(ah[t][0], ah[t][1], ah[t][2], ah[t][3], stg + O_AH * 2 + off);
                ldm_x4(al[t][0], al[t][1], al[t][2], al[t][3], stg + O_AL * 2 + off);
            }
#pragma unroll
            for (int j = 0; j < 2; j++) {
                uint32_t boff = (uint32_t)((((kk + bko) * BPITCH) + bno + j * 16) * 2);
                ldm_x4t(bh[2*j][0], bh[2*j][1], bh[2*j+1][0], bh[2*j+1][1],
                        stg + O_BH * 2 + boff);
                ldm_x4t(bl[2*j][0], bl[2*j][1], bl[2*j+1][0], bl[2*j+1][1],
                        stg + O_BL * 2 + boff);
            }
#pragma unroll
            for (int t = 0; t < 2; t++)
#pragma unroll
                for (int n = 0; n < 4; n++) {
                    mma_bf16(acc[t][n], ah[t][0], ah[t][1], ah[t][2], ah[t][3],
                             bh[n][0], bh[n][1]);
                    mma_bf16(acc[t][n], ah[t][0], ah[t][1], ah[t][2], ah[t][3],
                             bl[n][0], bl[n][1]);
                    mma_bf16(acc[t][n], al[t][0], al[t][1], al[t][2], al[t][3],
                             bh[n][0], bh[n][1]);
                }
        }
    }

#pragma unroll
    for (int t = 0; t < 2; t++) {
#pragma unroll
        for (int half = 0; half < 2; half++) {
            int grow = m0 + wm * 32 + t * 16 + gr + half * 8;
            int orow = (flags & 4) ? ((grow >> 6) * SEQ + map_base + (grow & 63)) : grow;
            float* crow = C + (size_t)orow * N;
#pragma unroll
            for (int n = 0; n < 4; n++) {
                int col = n0 + wn * 32 + n * 8 + qc * 2;
                float2 v;
                v.x = acc[t][n][half * 2 + 0];
                v.y = acc[t][n][half * 2 + 1];
                if (flags & 2) {
                    float2 b2 = *reinterpret_cast<const float2*>(bias + col);
                    v.x += b2.x; v.y += b2.y;
                }
                if (flags & 1) {
                    float2 o = *reinterpret_cast<const float2*>(crow + col);
                    v.x += o.x; v.y += o.y;
                }
                *reinterpret_cast<float2*>(crow + col) = v;
            }
        }
    }
#undef LOAD_A
#undef LDB
#undef STB
}

// contiguous split, 8 elems/thread, 16B stores (n%8==0)
__global__ void split_kernel(const float* __restrict__ src,
                             __nv_bfloat16* __restrict__ hi,
                             __nv_bfloat16* __restrict__ lo, size_t total8)
{
    size_t i8 = (size_t)blockIdx.x * blockDim.x + threadIdx.x;
    if (i8 >= total8) return;
    const float4* s4 = reinterpret_cast<const float4*>(src) + i8 * 2;
    float4 v0 = s4[0], v1 = s4[1];
    __align__(16) __nv_bfloat16 hb[8], lb[8];
    split_bf(v0.x, hb[0], lb[0]); split_bf(v0.y, hb[1], lb[1]);
    split_bf(v0.z, hb[2], lb[2]); split_bf(v0.w, hb[3], lb[3]);
    split_bf(v1.x, hb[4], lb[4]); split_bf(v1.y, hb[5], lb[5]);
    split_bf(v1.z, hb[6], lb[6]); split_bf(v1.w, hb[7], lb[7]);
    size_t o = i8 * 8;
    *reinterpret_cast<uint4*>(hi + o) = *reinterpret_cast<uint4*>(hb);
    *reinterpret_cast<uint4*>(lo + o) = *reinterpret_cast<uint4*>(lb);
}

__global__ void rope_table_kernel(float* __restrict__ cosb, float* __restrict__ sinb)
{
    int idx = blockIdx.x * blockDim.x + threadIdx.x;
    if (idx >= SEQ * 64) return;
    int s = idx >> 6, i = idx & 63;
    double inv = exp(-((double)(2 * i) / 128.0) * log(10000.0));
    double ang = (double)s * inv;
    cosb[idx] = (float)cos(ang);
    sinb[idx] = (float)sin(ang);
}

__global__ void embed_gather_kernel(const int* __restrict__ ids,
                                    const float* __restrict__ table,
                                    float* __restrict__ h)
{
    int idx = blockIdx.x * blockDim.x + threadIdx.x;
    if (idx >= B_ * SP * (DLLM / 4)) return;
    int d4 = idx & (DLLM / 4 - 1);
    int r = (idx / (DLLM / 4)) & (SP - 1);
    int b = idx / (SP * DLLM / 4);
    int id = ids[b * SP + r];
    reinterpret_cast<float4*>(h + ((size_t)(b * SEQ + r)) * DLLM)[d4] =
        reinterpret_cast<const float4*>(table + (size_t)id * DLLM)[d4];
}

__global__ __launch_bounds__(256) void rmsnorm_kernel(
    const float* __restrict__ x, const float* __restrict__ w, float* __restrict__ out)
{
    int t = blockIdx.x;
    const float4* xr = reinterpret_cast<const float4*>(x + (size_t)t * DLLM);
    float4 vals[4];
    float s = 0.f;
#pragma unroll
    for (int j = 0; j < 4; j++) {
        float4 v = xr[threadIdx.x + j * 256];
        vals[j] = v;
        s += v.x * v.x + v.y * v.y + v.z * v.z + v.w * v.w;
    }
#pragma unroll
    for (int off = 16; off > 0; off >>= 1) s += __shfl_xor_sync(0xffffffffu, s, off);
    __shared__ float red[8];
    __shared__ float sscale;
    if ((threadIdx.x & 31) == 0) red[threadIdx.x >> 5] = s;
    __syncthreads();
    if (threadIdx.x == 0) {
        float r = 0.f;
#pragma unroll
        for (int i = 0; i < 8; i++) r += red[i];
        sscale = rsqrtf(r * (1.0f / DLLM) + EPS);
    }
    __syncthreads();
    float sc = sscale;
    const float4* w4 = reinterpret_cast<const float4*>(w);
    float4* o4 = reinterpret_cast<float4*>(out + (size_t)t * DLLM);
#pragma unroll
    for (int j = 0; j < 4; j++) {
        float4 v = vals[j];
        float4 wv = w4[threadIdx.x + j * 256];
        o4[threadIdx.x + j * 256] = make_float4(
            v.x * sc * wv.x, v.y * sc * wv.y, v.z * sc * wv.z, v.w * sc * wv.w);
    }
}

__global__ __launch_bounds__(256) void rmsnorm_split_kernel(
    const float* __restrict__ x, const float* __restrict__ w,
    __nv_bfloat16* __restrict__ ohi, __nv_bfloat16* __restrict__ olo)
{
    int t = blockIdx.x;
    const float4* xr = reinterpret_cast<const float4*>(x + (size_t)t * DLLM);
    float4 vals[4];
    float s = 0.f;
#pragma unroll
    for (int j = 0; j < 4; j++) {
        float4 v = xr[threadIdx.x + j * 256];
        vals[j] = v;
        s += v.x * v.x + v.y * v.y + v.z * v.z + v.w * v.w;
    }
#pragma unroll
    for (int off = 16; off > 0; off >>= 1) s += __shfl_xor_sync(0xffffffffu, s, off);
    __shared__ float red[8];
    __shared__ float sscale;
    if ((threadIdx.x & 31) == 0) red[threadIdx.x >> 5] = s;
    __syncthreads();
    if (threadIdx.x == 0) {
        float r = 0.f;
#pragma unroll
        for (int i = 0; i < 8; i++) r += red[i];
        sscale = rsqrtf(r * (1.0f / DLLM) + EPS);
    }
    __syncthreads();
    float sc = sscale;
    const float4* w4 = reinterpret_cast<const float4*>(w);
    size_t base = (size_t)t * DLLM;
#pragma unroll
    for (int j = 0; j < 4; j++) {
        float4 v = vals[j];
        float4 wv = w4[threadIdx.x + j * 256];
        float rr[4] = { v.x * sc * wv.x, v.y * sc * wv.y, v.z * sc * wv.z, v.w * sc * wv.w };
        size_t o = base + ((size_t)threadIdx.x + j * 256) * 4;
        __align__(8) __nv_bfloat16 hb[4], lb[4];
#pragma unroll
        for (int e = 0; e < 4; e++) split_bf(rr[e], hb[e], lb[e]);
        *reinterpret_cast<uint2*>(ohi + o) = *reinterpret_cast<uint2*>(hb);
        *reinterpret_cast<uint2*>(olo + o) = *reinterpret_cast<uint2*>(lb);
    }
}

__global__ void rope_apply_kernel(float* __restrict__ qkv,
                                  const float* __restrict__ cosb,
                                  const float* __restrict__ sinb)
{
    int idx = blockIdx.x * blockDim.x + threadIdx.x;
    if (idx >= NTOK * NH * 64) return;
    int i = idx & 63;
    int h = (idx >> 6) & (NH - 1);
    int t = idx >> 11;
    int s = t & (SEQ - 1);
    float c = cosb[s * 64 + i];
    float sn = sinb[s * 64 + i];
    size_t base = (size_t)t * QKVS + h * HD + i;
    float x1 = qkv[base], x2 = qkv[base + 64];
    qkv[base]      = x1 * c - x2 * sn;
    qkv[base + 64] = x2 * c + x1 * sn;
    size_t kb = base + DLLM;
    x1 = qkv[kb]; x2 = qkv[kb + 64];
    qkv[kb]      = x1 * c - x2 * sn;
    qkv[kb + 64] = x2 * c + x1 * sn;
}

__global__ __launch_bounds__(256) void attention_kernel(
    const float* __restrict__ qkv,
    __nv_bfloat16* __restrict__ ohi, __nv_bfloat16* __restrict__ olo)
{
    __shared__ float sc[8][SEQ];
    const int b = blockIdx.z, hh = blockIdx.y;
    const int w = threadIdx.x >> 5, lane = threadIdx.x & 31;
    const int qi = blockIdx.x * 8 + w;
    const float scale = 0.088388347648318447f;

    const float* qrow = qkv + (size_t)(b * SEQ + qi) * QKVS + hh * HD;
    float4 qv = reinterpret_cast<const float4*>(qrow)[lane];

    const float* kbase = qkv + (size_t)b * SEQ * QKVS + DLLM + hh * HD;
    for (int kk = 0; kk <= qi; kk++) {
        float4 kv = reinterpret_cast<const float4*>(kbase + (size_t)kk * QKVS)[lane];
        float d = qv.x * kv.x + qv.y * kv.y + qv.z * kv.z + qv.w * kv.w;
#pragma unroll
        for (int off = 16; off > 0; off >>= 1) d += __shfl_xor_sync(0xffffffffu, d, off);
        if (lane == 0) sc[w][kk] = d * scale;
    }
    __syncwarp();

    float m = -1e30f;
    for (int kk = lane; kk <= qi; kk += 32) m = fmaxf(m, sc[w][kk]);
#pragma unroll
    for (int off = 16; off > 0; off >>= 1) m = fmaxf(m, __shfl_xor_sync(0xffffffffu, m, off));

    float ssum = 0.f;
    for (int kk = lane; kk <= qi; kk += 32) {
        float p = expf(sc[w][kk] - m);
        sc[w][kk] = p;
        ssum += p;
    }
#pragma unroll
    for (int off = 16; off > 0; off >>= 1) ssum += __shfl_xor_sync(0xffffffffu, ssum, off);
    __syncwarp();
    float inv = 1.0f / ssum;

    const float* vbase = qkv + (size_t)b * SEQ * QKVS + 2 * DLLM + hh * HD;
    float4 acc = make_float4(0.f, 0.f, 0.f, 0.f);
    for (int kk = 0; kk <= qi; kk++) {
        float p = sc[w][kk];
        float4 vv = reinterpret_cast<const float4*>(vbase + (size_t)kk * QKVS)[lane];
        acc.x += p * vv.x; acc.y += p * vv.y;
        acc.z += p * vv.z; acc.w += p * vv.w;
    }
    size_t o = (size_t)(b * SEQ + qi) * DLLM + hh * HD + lane * 4;
    float r[4] = { acc.x * inv, acc.y * inv, acc.z * inv, acc.w * inv };
    __align__(8) __nv_bfloat16 hb[4], lb[4];
#pragma unroll
    for (int e = 0; e < 4; e++) split_bf(r[e], hb[e], lb[e]);
    *reinterpret_cast<uint2*>(ohi + o) = *reinterpret_cast<uint2*>(hb);
    *reinterpret_cast<uint2*>(olo + o) = *reinterpret_cast<uint2*>(lb);
}

__global__ void silu_mul_split_kernel(const float* __restrict__ gu,
                                      __nv_bfloat16* __restrict__ ohi,
                                      __nv_bfloat16* __restrict__ olo, size_t total8)
{
    size_t i8 = (size_t)blockIdx.x * blockDim.x + threadIdx.x;
    if (i8 >= total8) return;
    const int D8 = DFF / 8;
    size_t t = i8 / D8;
    int j = (int)(i8 - t * D8) * 8;
    const float* row = gu + t * GUS;
    const float4* g4 = reinterpret_cast<const float4*>(row + j);
    const float4* u4 = reinterpret_cast<const float4*>(row + DFF + j);
    float4 g0 = g4[0], g1 = g4[1];
    float4 u0 = u4[0], u1 = u4[1];
    float rr[8] = {
        (g0.x / (1.0f + expf(-g0.x))) * u0.x,
        (g0.y / (1.0f + expf(-g0.y))) * u0.y,
        (g0.z / (1.0f + expf(-g0.z))) * u0.z,
        (g0.w / (1.0f + expf(-g0.w))) * u0.w,
        (g1.x / (1.0f + expf(-g1.x))) * u1.x,
        (g1.y / (1.0f + expf(-g1.y))) * u1.y,
        (g1.z / (1.0f + expf(-g1.z))) * u1.z,
        (g1.w / (1.0f + expf(-g1.w))) * u1.w
    };
    __align__(16) __nv_bfloat16 hb[8], lb[8];
#pragma unroll
    for (int e = 0; e < 8; e++) split_bf(rr[e], hb[e], lb[e]);
    size_t o = t * DFF + j;
    *reinterpret_cast<uint4*>(ohi + o) = *reinterpret_cast<uint4*>(hb);
    *reinterpret_cast<uint4*>(olo + o) = *reinterpret_cast<uint4*>(lb);
}

__global__ void pool_kernel(const float* __restrict__ xn, float* __restrict__ pooled)
{
    int idx = blockIdx.x * blockDim.x + threadIdx.x;
    if (idx >= B_ * DLLM) return;
    int b = idx >> 12, d = idx & (DLLM - 1);
    float s = 0.f;
    for (int t = 0; t < SEQ; t++)
        s += xn[(size_t)(b * SEQ + t) * DLLM + d];
    pooled[idx] = s * (1.0f / SEQ);
}

__global__ void head1_kernel(const float* __restrict__ pooled,
                             const float* __restrict__ W,
                             const float* __restrict__ bias,
                             float* __restrict__ y1)
{
    int b = blockIdx.x, j = threadIdx.x;
    const float* p = pooled + (size_t)b * DLLM;
    float s = bias[j];
    for (int i = 0; i < DLLM; i++) s += p[i] * W[(size_t)i * 768 + j];
    y1[b * 768 + j] = s;
}

__global__ void head2_kernel(const float* __restrict__ y1,
                             const float* __restrict__ W,
                             const float* __restrict__ bias,
                             float* __restrict__ out)
{
    int b = blockIdx.x;
    float s = 0.f;
    for (int j = threadIdx.x; j < 768; j += 256) s += y1[b * 768 + j] * W[j];
#pragma unroll
    for (int off = 16; off > 0; off >>= 1) s += __shfl_xor_sync(0xffffffffu, s, off);
    __shared__ float red[8];
    if ((threadIdx.x & 31) == 0) red[threadIdx.x >> 5] = s;
    __syncthreads();
    if (threadIdx.x == 0) {
        float r = 0.f;
#pragma unroll
        for (int i = 0; i < 8; i++) r += red[i];
        out[b] = r + bias[0];
    }
}

// ---------------------------------------------------------------------------
extern "C" void kernel_launch(void* const* d_in, const int* in_sizes, int n_in,
                              void* d_out, int out_size)
{
    const float* text  = (const float*)d_in[0];
    const float* vis   = (const float*)d_in[1];
    const int*   ids   = (const int*)  d_in[2];
    const float* inW   = (const float*)d_in[3];
    const float* inb   = (const float*)d_in[4];
    const float* etab  = (const float*)d_in[5];
    const float* Wq    = (const float*)d_in[6];
    const float* Wk    = (const float*)d_in[7];
    const float* Wv    = (const float*)d_in[8];
    const float* Wo    = (const float*)d_in[9];
    const float* ln1   = (const float*)d_in[10];
    const float* ln2   = (const float*)d_in[11];
    const float* Wg    = (const float*)d_in[12];
    const float* Wu    = (const float*)d_in[13];
    const float* Wd    = (const float*)d_in[14];
    const float* fnw   = (const float*)d_in[15];
    const float* o1W   = (const float*)d_in[16];
    const float* o1b   = (const float*)d_in[17];
    const float* o2W   = (const float*)d_in[18];
    const float* o2b   = (const float*)d_in[19];
    float* out = (float*)d_out;

    cudaFuncSetAttribute(gemm_tc, cudaFuncAttributeMaxDynamicSharedMemorySize,
                         GSMEM_BYTES);

    float* S = nullptr;
    cudaGetSymbolAddress((void**)&S, g_scratch);
    __nv_bfloat16* BS = nullptr;
    cudaGetSymbolAddress((void**)&BS, g_bf);

    float* h    = S + OFF_H;
    float* xn   = S + OFF_XN;
    float* qkv  = S + OFF_QKV;
    float* gu   = S + OFF_GU;
    float* cosb = S + OFF_COS;
    float* sinb = S + OFF_SIN;
    float* pooled = S + OFF_POOL;
    float* y1   = S + OFF_Y1;

    __nv_bfloat16 *xnh = BS + BO_XNH, *xnl = BS + BO_XNL;
    __nv_bfloat16 *ath = BS + BO_ATH, *atl = BS + BO_ATL;
    __nv_bfloat16 *gh  = BS + BO_GH,  *gl  = BS + BO_GL;
    __nv_bfloat16 *txh = BS + BO_TXH, *txl = BS + BO_TXL;
    __nv_bfloat16 *vxh = BS + BO_VXH, *vxl = BS + BO_VXL;

    const size_t W4s = (size_t)DLLM * DLLM;
    const size_t WFs = (size_t)DLLM * DFF;

    rope_table_kernel<<<(SEQ * 64 + 255) / 256, 256>>>(cosb, sinb);

    embed_gather_kernel<<<(B_ * SP * (DLLM / 4) + 255) / 256, 256>>>(ids, etab, h);
    split_kernel<<<(int)((SZ_TV / 8 + 255) / 256), 256>>>(text, txh, txl, SZ_TV / 8);
    split_kernel<<<(int)((SZ_TV / 8 + 255) / 256), 256>>>(vis, vxh, vxl, SZ_TV / 8);
    gemm_tc<<<dim3(DLLM / 64, 512 / 128), 256, GSMEM_BYTES>>>(
        txh, txl, inW, inW, inW, DLLM, h, 512, DLLM, DMODEL, 2 | 4, inb, SP);
    gemm_tc<<<dim3(DLLM / 64, 512 / 128), 256, GSMEM_BYTES>>>(
        vxh, vxl, inW, inW, inW, DLLM, h, 512, DLLM, DMODEL, 2 | 4, inb, SP + ST);

    for (int l = 0; l < 2; l++) {
        const float* wq = Wq + (size_t)l * W4s;
        const float* wk = Wk + (size_t)l * W4s;
        const float* wv = Wv + (size_t)l * W4s;
        const float* wo = Wo + (size_t)l * W4s;
        const float* wg = Wg + (size_t)l * WFs;
        const float* wu = Wu + (size_t)l * WFs;
        const float* wd = Wd + (size_t)l * WFs;

        rmsnorm_split_kernel<<<NTOK, 256>>>(h, ln1 + (size_t)l * DLLM, xnh, xnl);
        gemm_tc<<<dim3(QKVS / 64, NTOK / 128), 256, GSMEM_BYTES>>>(
            xnh, xnl, wq, wk, wv, DLLM, qkv, NTOK, QKVS, DLLM, 0, nullptr, 0);
        rope_apply_kernel<<<(NTOK * NH * 64 + 255) / 256, 256>>>(qkv, cosb, sinb);
        attention_kernel<<<dim3(SEQ / 8, NH, B_), 256>>>(qkv, ath, atl);
        gemm_tc<<<dim3(DLLM / 64, NTOK / 128), 256, GSMEM_BYTES>>>(
            ath, atl, wo, wo, wo, DLLM, h, NTOK, DLLM, DLLM, 1, nullptr, 0);

        rmsnorm_split_kernel<<<NTOK, 256>>>(h, ln2 + (size_t)l * DLLM, xnh, xnl);
        gemm_tc<<<dim3(GUS / 64, NTOK / 128), 256, GSMEM_BYTES>>>(
            xnh, xnl, wg, wu, wu, DFF, gu, NTOK, GUS, DLLM, 0, nullptr, 0);
        {
            size_t total8 = (size_t)NTOK * DFF / 8;
            silu_mul_split_kernel<<<(int)((total8 + 255) / 256), 256>>>(gu, gh, gl, total8);
        }
        gemm_tc<<<dim3(DLLM / 64, NTOK / 128), 256, GSMEM_BYTES>>>(
            gh, gl, wd, wd, wd, DLLM, h, NTOK, DLLM, DFF, 1, nullptr, 0);
    }

    rmsnorm_kernel<<<NTOK, 256>>>(h, fnw, xn);
    pool_kernel<<<(B_ * DLLM + 255) / 256, 256>>>(xn, pooled);
    head1_kernel<<<B_, 768>>>(pooled, o1W, o1b, y1);
    head2_kernel<<<B_, 256>>>(y1, o2W, o2b, out);
}